// round 12
// baseline (speedup 1.0000x reference)
#include <cuda_runtime.h>
#include <math.h>

#define BB 16
#define HH 512
#define WW 512
#define WORDS_PER_ROW 16     // 512 / 32  (u32 words)
#define QW_PER_ROW 8         // 512 / 64  (u64 words)
#define NBLK (32 * 16)       // 512 fused_edt blocks

// Scratch (no cudaMalloc allowed)
__device__ unsigned g_bits[BB * HH * WORDS_PER_ROW];  // 512 KB bitmask of gt!=0
__device__ float g_partial[NBLK];                     // per-strip partials
__device__ unsigned g_count;                          // last-block ticket (0-init)

// ---------------------------------------------------------------------------
// Kernel 1: pack gt (int32) -> bitmask. One thread per output BYTE (8 px).
// ---------------------------------------------------------------------------
__global__ void pack_bits(const int4* __restrict__ gt4) {
    int t = blockIdx.x * blockDim.x + threadIdx.x;   // one thread per 8 pixels
    int4 a = gt4[2 * t];
    int4 c = gt4[2 * t + 1];
    unsigned byte = (a.x != 0 ? 1u : 0u)  | (a.y != 0 ? 2u : 0u)
                  | (a.z != 0 ? 4u : 0u)  | (a.w != 0 ? 8u : 0u)
                  | (c.x != 0 ? 16u : 0u) | (c.y != 0 ? 32u : 0u)
                  | (c.z != 0 ? 64u : 0u) | (c.w != 0 ? 128u : 0u);
    ((unsigned char*)g_bits)[t] = (unsigned char)byte;
}

// ---------------------------------------------------------------------------
// Exact global fallback: scan full-image bitmask with distance pruning.
// Reachable only when no fg within radius 16 — correctness insurance.
// ---------------------------------------------------------------------------
__device__ __noinline__ float global_fallback(int b, int gi, int gj, float best) {
    const unsigned* base = g_bits + ((size_t)b * HH * WORDS_PER_ROW);
    for (int dd = 0; dd < HH; ++dd) {
        float dd2 = (float)(dd * dd);
        if (dd2 >= best) break;
        for (int sgn = 0; sgn < 2; ++sgn) {
            if (sgn && dd == 0) continue;
            int r = sgn ? gi + dd : gi - dd;
            if (r < 0 || r >= HH) continue;
            const unsigned* row = base + r * WORDS_PER_ROW;
            for (int w = 0; w < WORDS_PER_ROW; ++w) {
                unsigned word = row[w];
                while (word) {
                    int bit = __ffs(word) - 1;
                    word &= word - 1;
                    float dj = (float)((w << 5) + bit - gj);
                    best = fminf(best, dd2 + dj * dj);
                }
            }
        }
    }
    return best;
}

// ---------------------------------------------------------------------------
// Cold path (P ~ 2^-25 per pixel): exact expanding-Chebyshev-ring search over
// the 48-row strip window via direct bit tests, then exact global fallback.
// lr in [16,31] so lr +- 16 stays in [0,47].
// ---------------------------------------------------------------------------
__device__ __forceinline__ int bit_at(const unsigned long long* s, int row, int col) {
    if (col < 0 || col >= WW) return 0;
    return (int)((s[row * QW_PER_ROW + (col >> 6)] >> (col & 63)) & 1ull);
}

__device__ __noinline__ float ring_search_strip(const unsigned long long* s,
                                                int lr, int c, int b, int gi) {
    float best = 1e30f;
    for (int r = 3; r <= 16; ++r) {
        float rr = (float)(r * r);
        if (rr >= best) break;
        for (int dj = -r; dj <= r; ++dj) {
            if (bit_at(s, lr - r, c + dj) | bit_at(s, lr + r, c + dj))
                best = fminf(best, rr + (float)(dj * dj));
        }
        for (int di = -(r - 1); di <= r - 1; ++di) {
            if (bit_at(s, lr + di, c - r) | bit_at(s, lr + di, c + r))
                best = fminf(best, rr + (float)(di * di));
        }
    }
    if (best > 289.0f)
        best = global_fallback(b, gi, c, best);
    return best;
}

// ---------------------------------------------------------------------------
// Kernel 2: fused exact EDT + sqrt + probs multiply + full reduction.
// Block = 16-row x 512-col strip. Window = 48 rows x 512 bits (3 KB smem),
// filled by all 256 threads. Thread = 1 row x 32 cols in 8 groups of 4:
// per group one float4 probs load (MLP=8) + 5 two-word bit extracts + the
// branchless 5x5 classifier (d^2 in {0,1,2,4,5,8}); cold path exact.
// Grid: (32 strips, 16 batches); block 256. Single wave on 148 SMs.
// ---------------------------------------------------------------------------
__global__ void fused_edt(const float* __restrict__ probs,
                          float* __restrict__ out) {
    __shared__ unsigned long long s[48 * QW_PER_ROW];   // 3 KB
    __shared__ float wsum[8];
    __shared__ int is_last;

    int st  = blockIdx.x;            // strip index, 0..31
    int b   = blockIdx.y;            // batch
    int r0  = st * 16;               // first image row of strip
    int tid = threadIdx.x;

    // Fill window rows [r0-16, r0+32); outside image = 0.
    const unsigned long long* bits64 =
        (const unsigned long long*)g_bits + (size_t)b * HH * QW_PER_ROW;
    #pragma unroll
    for (int idx = tid; idx < 48 * QW_PER_ROW; idx += 256) {
        int row = idx >> 3;          // 0..47
        int w   = idx & 7;
        int gi  = r0 - 16 + row;
        s[idx] = (gi >= 0 && gi < HH) ? bits64[gi * QW_PER_ROW + w] : 0ull;
    }
    __syncthreads();

    int row = tid >> 4;              // 0..15, row within strip
    int cg  = tid & 15;              // column group (32 cols each... 4*? see below)
    int lr  = 16 + row;              // local window row
    int gi  = r0 + row;              // global image row

    const float* prow = probs + (((size_t)b * 2) * HH + gi) * WW;

    float acc = 0.0f;
    #pragma unroll
    for (int g = 0; g < 8; ++g) {
        int cbase = g * 64 + cg * 4;         // 0..508, multiple of 4
        // probs: one float4 per group; lanes 0..15 contiguous 256B
        float4 p4 = *(const float4*)&prow[cbase];
        float pv[4] = {p4.x, p4.y, p4.z, p4.w};

        // Extract 8-bit fields for 5 rows: bit i = col (cbase - 2 + i)
        unsigned ext[5];
        int bp = cbase - 2;
        if (bp < 0) {                          // only g==0 && cg==0
            #pragma unroll
            for (int m = 0; m < 5; ++m)
                ext[m] = (unsigned)(s[(lr - 2 + m) * QW_PER_ROW] << 2) & 0xFFu;
        } else {
            int w   = bp >> 6;
            int off = bp & 63;                 // in [2, 62], never 0
            #pragma unroll
            for (int m = 0; m < 5; ++m) {
                const unsigned long long* sr = s + (lr - 2 + m) * QW_PER_ROW;
                unsigned long long lo = sr[w];
                unsigned long long hi = (w < QW_PER_ROW - 1) ? sr[w + 1] : 0ull;
                ext[m] = (unsigned)((lo >> off) | (hi << (64 - off))) & 0xFFu;
            }
        }
        unsigned a8  = ext[2];
        unsigned c1r = ext[1] | ext[3];
        unsigned c2r = ext[0] | ext[4];

        #pragma unroll
        for (int k = 0; k < 4; ++k) {
            unsigned a5 = (a8  >> k) & 31u;
            unsigned c1 = (c1r >> k) & 31u;
            unsigned c2 = (c2r >> k) & 31u;

            unsigned h0 = a5 & 0x4u;                              // d^2 = 0
            unsigned h1 = (a5 & 0xAu)  | (c1 & 0x4u);             // d^2 = 1
            unsigned h2 = c1 & 0xAu;                              // d^2 = 2
            unsigned h4 = (a5 & 0x11u) | (c2 & 0x4u);             // d^2 = 4
            unsigned h5 = (c1 & 0x11u) | (c2 & 0xAu);             // d^2 = 5
            unsigned h8 = c2 & 0x11u;                             // d^2 = 8

            float dist;
            if (h0 | h1 | h2 | h4 | h5 | h8) {
                dist = h0 ? 0.0f
                     : h1 ? 1.0f
                     : h2 ? 1.41421356237309515f    // sqrt(2)
                     : h4 ? 2.0f
                     : h5 ? 2.23606797749978981f    // sqrt(5)
                     :      2.82842712474619029f;   // sqrt(8)
            } else {
                dist = sqrtf(ring_search_strip(s, lr, cbase + k, b, gi));
            }
            acc += dist * pv[k];
        }
    }

    // deterministic block reduction (8 warps)
    #pragma unroll
    for (int off = 16; off > 0; off >>= 1)
        acc += __shfl_down_sync(0xffffffffu, acc, off);
    if ((tid & 31) == 0) wsum[tid >> 5] = acc;
    __syncthreads();
    if (tid < 8) {
        float v = wsum[tid];
        #pragma unroll
        for (int off = 4; off > 0; off >>= 1)
            v += __shfl_down_sync(0x000000ffu, v, off);
        if (tid == 0) {
            g_partial[blockIdx.y * 32 + blockIdx.x] = v;
            __threadfence();
            unsigned ticket = atomicAdd(&g_count, 1u);
            is_last = (ticket == NBLK - 1);
        }
    }
    __syncthreads();

    // Last block reduces all partials in a fixed order (deterministic).
    if (is_last) {
        __threadfence();
        float v = (tid < NBLK) ? g_partial[tid] : 0.0f;
        v += (tid + 256 < NBLK) ? g_partial[tid + 256] : 0.0f;
        #pragma unroll
        for (int off = 16; off > 0; off >>= 1)
            v += __shfl_down_sync(0xffffffffu, v, off);
        if ((tid & 31) == 0) wsum[tid >> 5] = v;
        __syncthreads();
        if (tid < 8) {
            float w = wsum[tid];
            #pragma unroll
            for (int off = 4; off > 0; off >>= 1)
                w += __shfl_down_sync(0x000000ffu, w, off);
            if (tid == 0) {
                out[0] = w * (1.0f / (float)((size_t)BB * HH * WW));
                g_count = 0;   // self-reset for graph replay
            }
        }
    }
}

extern "C" void kernel_launch(void* const* d_in, const int* in_sizes, int n_in,
                              void* d_out, int out_size) {
    const float* probs = (const float*)d_in[0];
    const int*   gt    = (const int*)d_in[1];
    float* out = (float*)d_out;

    // one thread per 8 pixels: 4194304 / 8 / 256 = 2048 blocks
    pack_bits<<<2048, 256>>>((const int4*)gt);
    dim3 grid(32, BB);
    fused_edt<<<grid, 256>>>(probs, out);
}

// round 13
// speedup vs baseline: 1.6500x; 1.6500x over previous
#include <cuda_runtime.h>
#include <math.h>

#define BB 16
#define HH 512
#define WW 512
#define WORDS_PER_ROW 16     // 512 / 32 (u32 words)
#define SROW 17              // smem row stride: 16 words + 1 zero pad
#define WROWS 40             // window rows: 8 strip rows + 2*16 halo
#define NBLK (64 * 16)       // 1024 fused_edt blocks

// Scratch (no cudaMalloc allowed)
__device__ unsigned g_bits[BB * HH * WORDS_PER_ROW];  // 512 KB bitmask of gt!=0
__device__ float g_partial[NBLK];                     // per-strip partials
__device__ unsigned g_count;                          // last-block ticket (0-init)

// ---------------------------------------------------------------------------
// Kernel 1: pack gt (int32) -> bitmask. One thread per output BYTE (8 px).
// ---------------------------------------------------------------------------
__global__ void pack_bits(const int4* __restrict__ gt4) {
    int t = blockIdx.x * blockDim.x + threadIdx.x;   // one thread per 8 pixels
    int4 a = gt4[2 * t];
    int4 c = gt4[2 * t + 1];
    unsigned byte = (a.x != 0 ? 1u : 0u)  | (a.y != 0 ? 2u : 0u)
                  | (a.z != 0 ? 4u : 0u)  | (a.w != 0 ? 8u : 0u)
                  | (c.x != 0 ? 16u : 0u) | (c.y != 0 ? 32u : 0u)
                  | (c.z != 0 ? 64u : 0u) | (c.w != 0 ? 128u : 0u);
    ((unsigned char*)g_bits)[t] = (unsigned char)byte;
}

// ---------------------------------------------------------------------------
// Exact global fallback: scan full-image bitmask with distance pruning.
// Reachable only when no fg within radius 16 — correctness insurance.
// ---------------------------------------------------------------------------
__device__ __noinline__ float global_fallback(int b, int gi, int gj, float best) {
    const unsigned* base = g_bits + ((size_t)b * HH * WORDS_PER_ROW);
    for (int dd = 0; dd < HH; ++dd) {
        float dd2 = (float)(dd * dd);
        if (dd2 >= best) break;
        for (int sgn = 0; sgn < 2; ++sgn) {
            if (sgn && dd == 0) continue;
            int r = sgn ? gi + dd : gi - dd;
            if (r < 0 || r >= HH) continue;
            const unsigned* row = base + r * WORDS_PER_ROW;
            for (int w = 0; w < WORDS_PER_ROW; ++w) {
                unsigned word = row[w];
                while (word) {
                    int bit = __ffs(word) - 1;
                    word &= word - 1;
                    float dj = (float)((w << 5) + bit - gj);
                    best = fminf(best, dd2 + dj * dj);
                }
            }
        }
    }
    return best;
}

// ---------------------------------------------------------------------------
// Cold path (P ~ 2^-25 per pixel): exact expanding-Chebyshev-ring search over
// the 40-row strip window, then exact global fallback. lr in [16,23] so
// lr +- 16 stays in [0,39].
// ---------------------------------------------------------------------------
__device__ __forceinline__ int bit_at(const unsigned* s, int row, int col) {
    if (col < 0 || col >= WW) return 0;
    return (int)((s[row * SROW + (col >> 5)] >> (col & 31)) & 1u);
}

__device__ __noinline__ float ring_search_strip(const unsigned* s,
                                                int lr, int c, int b, int gi) {
    float best = 1e30f;
    for (int r = 3; r <= 16; ++r) {
        float rr = (float)(r * r);
        if (rr >= best) break;
        for (int dj = -r; dj <= r; ++dj) {
            if (bit_at(s, lr - r, c + dj) | bit_at(s, lr + r, c + dj))
                best = fminf(best, rr + (float)(dj * dj));
        }
        for (int di = -(r - 1); di <= r - 1; ++di) {
            if (bit_at(s, lr + di, c - r) | bit_at(s, lr + di, c + r))
                best = fminf(best, rr + (float)(di * di));
        }
    }
    if (best > 289.0f)
        best = global_fallback(b, gi, c, best);
    return best;
}

// ---------------------------------------------------------------------------
// Kernel 2: fused exact EDT + sqrt + probs multiply + full reduction.
// Block = 8-row x 512-col strip; window = 40 rows of bits in smem (u32 + pad).
// Thread = 1 row x 16 cols. Word-wide cumulative class masks M(d^2<=X) built
// once per thread (~28 u32 ops for 16 px), then a branch-free 16x unrolled
// select chain. Cold pixels = ~M8 bitmask, handled after the loop (exact).
// Grid: (64 strips, 16 batches) = 1024 blocks; block 256.
// ---------------------------------------------------------------------------
__global__ void fused_edt(const float* __restrict__ probs,
                          float* __restrict__ out) {
    __shared__ unsigned s[WROWS * SROW];   // 2720 B
    __shared__ float wsum[8];
    __shared__ int is_last;

    int st  = blockIdx.x;            // strip index, 0..63
    int b   = blockIdx.y;            // batch
    int r0  = st * 8;                // first image row of strip
    int tid = threadIdx.x;

    // Fill window rows [r0-16, r0+24); outside image = 0; pad word = 0.
    const unsigned* bits = g_bits + (size_t)b * HH * WORDS_PER_ROW;
    for (int idx = tid; idx < WROWS * SROW; idx += 256) {
        int row = idx / SROW;
        int w   = idx - row * SROW;
        int gi  = r0 - 16 + row;
        s[idx] = (w < 16 && gi >= 0 && gi < HH) ? bits[gi * WORDS_PER_ROW + w] : 0u;
    }
    __syncthreads();

    int row = tid >> 5;              // 0..7, row within strip
    int cg  = tid & 31;              // column group, 16 cols each
    int lr  = 16 + row;              // local window row
    int gi  = r0 + row;              // global image row
    int c0  = cg * 16;               // first column of this thread

    // Extract 5 row-fields: bit j of F[m] = column (c0 - 2 + j).
    // off = c0-2; for cg=0 shift left instead (cols <0 read as 0).
    unsigned F[5];
    {
        int off = c0 - 2;
        int w   = (off < 0) ? 0 : (off >> 5);
        int sh  = off & 31;
        #pragma unroll
        for (int m = 0; m < 5; ++m) {
            const unsigned* sr = s + (lr - 2 + m) * SROW;
            unsigned lo = sr[w], hi = sr[w + 1];
            F[m] = (cg == 0) ? (sr[0] << 2) : __funnelshift_r(lo, hi, sh);
        }
    }
    unsigned A  = F[2];
    unsigned C1 = F[1] | F[3];
    unsigned C2 = F[0] | F[4];

    // Cumulative masks: bit j set iff exists fg with d^2 <= X at col c0-2+j.
    unsigned M0 = A;
    unsigned M1 = M0 | (A << 1)  | (A >> 1)  | C1;
    unsigned M2 = M1 | (C1 << 1) | (C1 >> 1);
    unsigned M4 = M2 | (A << 2)  | (A >> 2)  | C2;
    unsigned M5 = M4 | (C1 << 2) | (C1 >> 2) | (C2 << 1) | (C2 >> 1);
    unsigned M8 = M5 | (C2 << 2) | (C2 >> 2);

    // Align: bit p = pixel (c0 + p), p = 0..15.
    unsigned a0 = M0 >> 2, a1 = M1 >> 2, a2 = M2 >> 2,
             a4 = M4 >> 2, a5 = M5 >> 2, a8 = M8 >> 2;
    unsigned coldmask = ~a8 & 0xFFFFu;   // pixels with no fg in 5x5 (rare)

    // probs layout [B, 2, H, W] channel 0; 4 x float4 = 16 contiguous floats.
    const float* prow = probs + (((size_t)b * 2) * HH + gi) * WW;
    float4 p0 = *(const float4*)&prow[c0];
    float4 p1 = *(const float4*)&prow[c0 + 4];
    float4 p2 = *(const float4*)&prow[c0 + 8];
    float4 p3 = *(const float4*)&prow[c0 + 12];
    float pv[16] = {p0.x, p0.y, p0.z, p0.w, p1.x, p1.y, p1.z, p1.w,
                    p2.x, p2.y, p2.z, p2.w, p3.x, p3.y, p3.z, p3.w};

    float acc = 0.0f;
    #pragma unroll
    for (int p = 0; p < 16; ++p) {
        unsigned bit = 1u << p;
        // widest-to-narrowest overwrite; cumulative masks => narrower wins
        float dist = (a8 & bit) ? 2.82842712474619029f : 0.0f;  // sqrt(8)
        dist = (a5 & bit) ? 2.23606797749978981f : dist;        // sqrt(5)
        dist = (a4 & bit) ? 2.0f : dist;
        dist = (a2 & bit) ? 1.41421356237309515f : dist;        // sqrt(2)
        dist = (a1 & bit) ? 1.0f : dist;
        dist = (a0 & bit) ? 0.0f : dist;
        acc += dist * pv[p];
    }

    // Deferred exact handling of cold pixels (essentially never taken).
    while (coldmask) {
        int p = __ffs(coldmask) - 1;
        coldmask &= coldmask - 1;
        float dist = sqrtf(ring_search_strip(s, lr, c0 + p, b, gi));
        acc += dist * prow[c0 + p];
    }

    // deterministic block reduction (8 warps)
    #pragma unroll
    for (int off = 16; off > 0; off >>= 1)
        acc += __shfl_down_sync(0xffffffffu, acc, off);
    if ((tid & 31) == 0) wsum[tid >> 5] = acc;
    __syncthreads();
    if (tid < 8) {
        float v = wsum[tid];
        #pragma unroll
        for (int off = 4; off > 0; off >>= 1)
            v += __shfl_down_sync(0x000000ffu, v, off);
        if (tid == 0) {
            g_partial[blockIdx.y * 64 + blockIdx.x] = v;
            __threadfence();
            unsigned ticket = atomicAdd(&g_count, 1u);
            is_last = (ticket == NBLK - 1);
        }
    }
    __syncthreads();

    // Last block reduces all partials in a fixed order (deterministic).
    if (is_last) {
        __threadfence();
        float v = g_partial[tid] + g_partial[tid + 256]
                + g_partial[tid + 512] + g_partial[tid + 768];
        #pragma unroll
        for (int off = 16; off > 0; off >>= 1)
            v += __shfl_down_sync(0xffffffffu, v, off);
        if ((tid & 31) == 0) wsum[tid >> 5] = v;
        __syncthreads();
        if (tid < 8) {
            float w = wsum[tid];
            #pragma unroll
            for (int off = 4; off > 0; off >>= 1)
                w += __shfl_down_sync(0x000000ffu, w, off);
            if (tid == 0) {
                out[0] = w * (1.0f / (float)((size_t)BB * HH * WW));
                g_count = 0;   // self-reset for graph replay
            }
        }
    }
}

extern "C" void kernel_launch(void* const* d_in, const int* in_sizes, int n_in,
                              void* d_out, int out_size) {
    const float* probs = (const float*)d_in[0];
    const int*   gt    = (const int*)d_in[1];
    float* out = (float*)d_out;

    // one thread per 8 pixels: 4194304 / 8 / 256 = 2048 blocks
    pack_bits<<<2048, 256>>>((const int4*)gt);
    dim3 grid(64, BB);
    fused_edt<<<grid, 256>>>(probs, out);
}